// round 2
// baseline (speedup 1.0000x reference)
#include <cuda_runtime.h>
#include <cuda_bf16.h>

#define BB 4
#define NN 10000
#define MM 10000
#define PP 128
#define KS 32
#define ZF 128

// ---------------- device scratch (static: no allocation) ----------------
__device__ float4 g_noisy4[BB * NN];      // (x,y,z, x^2+y^2+z^2)
__device__ float4 g_clean4[BB * MM];
__device__ float4 g_forigin[BB * PP];
__device__ float  g_zpart[BB * PP * ZF];  // Ws1[3:]^T z + bs1 per (b,p)
__device__ float4 g_fpts[BB * PP * KS];   // gathered noisy neighbors
__device__ float  g_estim[BB * PP * KS * 3];
__device__ float  g_partial[BB * PP];

__device__ __forceinline__ float finf() { return __int_as_float(0x7f800000); }

// ---------------- K0: pack point clouds as float4 with |r|^2 ----------------
__global__ void k0_pack(const float* __restrict__ noisy, const float* __restrict__ clean) {
    int i = blockIdx.x * blockDim.x + threadIdx.x;
    if (i < BB * NN) {
        float x = noisy[i * 3 + 0], y = noisy[i * 3 + 1], z = noisy[i * 3 + 2];
        g_noisy4[i] = make_float4(x, y, z, fmaf(x, x, fmaf(y, y, z * z)));
    }
    if (i < BB * MM) {
        float x = clean[i * 3 + 0], y = clean[i * 3 + 1], z = clean[i * 3 + 2];
        g_clean4[i] = make_float4(x, y, z, fmaf(x, x, fmaf(y, y, z * z)));
    }
}

// ---------------- K1: f_origin, feat(sampled), zpart ----------------
__global__ void k1_feat(const float* __restrict__ noisy, const int* __restrict__ sidx,
                        const float* __restrict__ Wf1, const float* __restrict__ bf1,
                        const float* __restrict__ Wf2, const float* __restrict__ bf2,
                        const float* __restrict__ Ws1, const float* __restrict__ bs1) {
    int bp = blockIdx.x;            // 0..511
    int b = bp >> 7, p = bp & 127;
    int tid = threadIdx.x;          // 128 threads
    __shared__ float xyz[3];
    __shared__ float h[64];
    __shared__ float z[128];

    if (tid == 0) {
        int si = sidx[p];
        const float* s = noisy + ((size_t)b * NN + si) * 3;
        xyz[0] = s[0]; xyz[1] = s[1]; xyz[2] = s[2];
        g_forigin[bp] = make_float4(s[0], s[1], s[2], 0.f);
    }
    __syncthreads();

    if (tid < 64) {
        float a = bf1[tid];
        a = fmaf(xyz[0], Wf1[0 * 64 + tid], a);
        a = fmaf(xyz[1], Wf1[1 * 64 + tid], a);
        a = fmaf(xyz[2], Wf1[2 * 64 + tid], a);
        h[tid] = fmaxf(a, 0.f);
    }
    __syncthreads();

    {
        float a = bf2[tid];
#pragma unroll 16
        for (int i = 0; i < 64; ++i) a = fmaf(h[i], Wf2[i * 128 + tid], a);
        z[tid] = a;                 // feat: no relu on second layer
    }
    __syncthreads();

    {
        float a = bs1[tid];
#pragma unroll 16
        for (int i = 0; i < 128; ++i) a = fmaf(z[i], Ws1[(3 + i) * 128 + tid], a);
        g_zpart[bp * ZF + tid] = a;
    }
}

// ---------------- K2: KNN1 top-32 via threshold binary search ----------------
__global__ __launch_bounds__(256) void k2_knn1() {
    int bp = blockIdx.x;            // one query per block
    int b = bp >> 7;
    int tid = threadIdx.x;
    __shared__ unsigned keys[NN];   // 40 KB
    __shared__ unsigned s_cnt;

    float4 q = g_forigin[bp];
    float m2x = -2.0f * q.x, m2y = -2.0f * q.y, m2z = -2.0f * q.z;
    for (int r = tid; r < NN; r += 256) {
        float4 v = g_noisy4[b * NN + r];
        float s = fmaf(v.x, m2x, fmaf(v.y, m2y, fmaf(v.z, m2z, v.w))); // d2 - |q|^2
        unsigned u = __float_as_uint(s);
        u ^= ((unsigned)((int)u >> 31)) | 0x80000000u;  // monotone float->uint
        keys[r] = u;
    }
    __syncthreads();

    unsigned lo = 0u, hi = 0xFFFFFFFFu;
    for (int it = 0; it < 34 && lo + 1u < hi; ++it) {
        unsigned mid = lo + ((hi - lo) >> 1);
        if (tid == 0) s_cnt = 0;
        __syncthreads();
        unsigned c = 0;
        for (int r = tid; r < NN; r += 256) c += (keys[r] <= mid);
        c = __reduce_add_sync(0xFFFFFFFFu, c);
        if ((tid & 31) == 0) atomicAdd(&s_cnt, c);
        __syncthreads();
        unsigned cnt = s_cnt;
        __syncthreads();
        if (cnt >= 32u) { hi = mid; if (cnt == 32u) break; }
        else lo = mid;
    }
    unsigned T = hi;   // count(keys <= T) >= 32 (== 32 for distinct values)

    if (tid == 0) s_cnt = 0;
    __syncthreads();
    for (int r = tid; r < NN; r += 256) {
        if (keys[r] <= T) {
            unsigned pos = atomicAdd(&s_cnt, 1u);
            if (pos < 32u) g_fpts[bp * KS + pos] = g_noisy4[b * NN + r];
        }
    }
}

// ---------------- K3: score MLP, 2 bp per block, pipelined weight loads ----------
__global__ __launch_bounds__(256) void k3_mlp(const float* __restrict__ Ws1,
                                              const float* __restrict__ Ws2,
                                              const float* __restrict__ bs2,
                                              const float* __restrict__ Ws3,
                                              const float* __restrict__ bs3) {
    int bp0 = blockIdx.x * 2;
    int tid = threadIdx.x;          // 256 threads
    int half = tid >> 7;            // which bp of the pair
    int t = tid & 127;              // within-half thread (feature id in layer 1)
    int bp = bp0 + half;

    __shared__ float xs[2][KS][4];
    __shared__ float hbuf[2][KS * 129];   // h1 (stride 129), later overlaid by h2 (stride 66)

    float4 o4 = g_forigin[bp];
    if (t < 32) {
        float4 f = g_fpts[bp * KS + t];
        xs[half][t][0] = f.x - o4.x;
        xs[half][t][1] = f.y - o4.y;
        xs[half][t][2] = f.z - o4.z;
    }
    float zp = g_zpart[bp * ZF + t];
    float w0 = Ws1[0 * 128 + t], w1 = Ws1[1 * 128 + t], w2 = Ws1[2 * 128 + t];
    __syncthreads();

    // layer 1: h1 = relu(x0*w0 + x1*w1 + x2*w2 + zpart)
#pragma unroll
    for (int k = 0; k < KS; ++k) {
        float a = fmaf(xs[half][k][2], w2, fmaf(xs[half][k][1], w1, fmaf(xs[half][k][0], w0, zp)));
        hbuf[half][k * 129 + t] = fmaxf(a, 0.f);
    }
    __syncthreads();

    // layer 2: lane = k, warp = (half, output-quarter)
    int k = tid & 31, oq = (tid >> 5) & 3;
    float acc[16];
#pragma unroll
    for (int j = 0; j < 16; ++j) acc[j] = bs2[oq * 16 + j];
    {
        const float* hrow = &hbuf[half][k * 129];
        const float4* __restrict__ wbase = (const float4*)(Ws2 + oq * 16);
#pragma unroll 4
        for (int i = 0; i < 128; ++i) {
            float hv = hrow[i];
            float4 wa = wbase[i * 16 + 0];
            float4 wb = wbase[i * 16 + 1];
            float4 wc = wbase[i * 16 + 2];
            float4 wd = wbase[i * 16 + 3];
            acc[0]  = fmaf(hv, wa.x, acc[0]);  acc[1]  = fmaf(hv, wa.y, acc[1]);
            acc[2]  = fmaf(hv, wa.z, acc[2]);  acc[3]  = fmaf(hv, wa.w, acc[3]);
            acc[4]  = fmaf(hv, wb.x, acc[4]);  acc[5]  = fmaf(hv, wb.y, acc[5]);
            acc[6]  = fmaf(hv, wb.z, acc[6]);  acc[7]  = fmaf(hv, wb.w, acc[7]);
            acc[8]  = fmaf(hv, wc.x, acc[8]);  acc[9]  = fmaf(hv, wc.y, acc[9]);
            acc[10] = fmaf(hv, wc.z, acc[10]); acc[11] = fmaf(hv, wc.w, acc[11]);
            acc[12] = fmaf(hv, wd.x, acc[12]); acc[13] = fmaf(hv, wd.y, acc[13]);
            acc[14] = fmaf(hv, wd.z, acc[14]); acc[15] = fmaf(hv, wd.w, acc[15]);
        }
    }
    __syncthreads();     // everyone done READING h1 — safe to overlay h2
#pragma unroll
    for (int j = 0; j < 16; ++j)
        hbuf[half][k * 66 + oq * 16 + j] = fmaxf(acc[j], 0.f);
    __syncthreads();

    // layer 3: 96 threads per half
    if (tid < 192) {
        int hh = tid / 96, r = tid % 96;
        int kk = r / 3, d = r % 3;
        float a = bs3[d];
#pragma unroll 16
        for (int i = 0; i < 64; ++i) a = fmaf(hbuf[hh][kk * 66 + i], Ws3[i * 3 + d], a);
        g_estim[((bp0 + hh) * KS + kk) * 3 + d] = a;
    }
}

// insertion into sorted 4-element top list
#define INS4(s, id, s0, s1, s2, s3, i0, i1, i2, i3)             \
    if ((s) < (s3)) {                                           \
        if ((s) < (s2)) {                                       \
            (s3) = (s2); (i3) = (i2);                           \
            if ((s) < (s1)) {                                   \
                (s2) = (s1); (i2) = (i1);                       \
                if ((s) < (s0)) { (s1) = (s0); (i1) = (i0); (s0) = (s); (i0) = (id); } \
                else { (s1) = (s); (i1) = (id); }               \
            } else { (s2) = (s); (i2) = (id); }                 \
        } else { (s3) = (s); (i3) = (id); }                     \
    }

// ---------------- K4: KNN2 top-4 + ground score + loss partials ----------------
__global__ __launch_bounds__(256) void k4_knn2() {
    int bp = blockIdx.x;
    int b = bp >> 7;
    int tid = threadIdx.x, lane = tid & 31, w = tid >> 5;   // 8 warps
    __shared__ float4 buf[2048];                 // 32 KB tile
    __shared__ float  cs[8][32][4];
    __shared__ int    ci[8][32][4];

    float4 f = g_fpts[bp * KS + lane];           // lane = query k
    float m2x = -2.0f * f.x, m2y = -2.0f * f.y, m2z = -2.0f * f.z;
    float s0 = finf(), s1 = finf(), s2 = finf(), s3 = finf();
    int   i0 = 0, i1 = 0, i2 = 0, i3 = 0;

    for (int t0 = 0; t0 < MM; t0 += 2048) {
        int n = min(2048, MM - t0);
        __syncthreads();
        for (int j = tid; j < n; j += 256) buf[j] = g_clean4[b * MM + t0 + j];
        __syncthreads();
        int chunk = (n + 7) >> 3;
        int start = w * chunk;
        int end = min(start + chunk, n);
#pragma unroll 4
        for (int r = start; r < end; ++r) {
            float4 v = buf[r];                   // broadcast LDS.128
            float s = fmaf(v.x, m2x, fmaf(v.y, m2y, fmaf(v.z, m2z, v.w)));
            int id = t0 + r;
            INS4(s, id, s0, s1, s2, s3, i0, i1, i2, i3);
        }
    }
    cs[w][lane][0] = s0; cs[w][lane][1] = s1; cs[w][lane][2] = s2; cs[w][lane][3] = s3;
    ci[w][lane][0] = i0; ci[w][lane][1] = i1; ci[w][lane][2] = i2; ci[w][lane][3] = i3;
    __syncthreads();

    if (w == 0) {
        float b0 = finf(), b1 = finf(), b2 = finf(), b3 = finf();
        int   j0 = 0, j1 = 0, j2 = 0, j3 = 0;
#pragma unroll
        for (int ww = 0; ww < 8; ++ww)
#pragma unroll
            for (int jj = 0; jj < 4; ++jj) {
                float s = cs[ww][lane][jj];
                int id = ci[ww][lane][jj];
                INS4(s, id, b0, b1, b2, b3, j0, j1, j2, j3);
            }
        float4 c0 = g_clean4[b * MM + j0];
        float4 c1 = g_clean4[b * MM + j1];
        float4 c2 = g_clean4[b * MM + j2];
        float4 c3 = g_clean4[b * MM + j3];
        float gx = (c0.x + c1.x + c2.x + c3.x) * 0.25f - f.x;
        float gy = (c0.y + c1.y + c2.y + c3.y) * 0.25f - f.y;
        float gz = (c0.z + c1.z + c2.z + c3.z) * 0.25f - f.z;
        const float* e = g_estim + (bp * KS + lane) * 3;
        float d0 = e[0] - gx, d1 = e[1] - gy, d2v = e[2] - gz;
        float err = fmaf(d0, d0, fmaf(d1, d1, d2v * d2v));
#pragma unroll
        for (int off = 16; off > 0; off >>= 1)
            err += __shfl_xor_sync(0xFFFFFFFFu, err, off);
        if (lane == 0) g_partial[bp] = err;
    }
}

// ---------------- K5: deterministic final reduce ----------------
__global__ void k5_reduce(float* __restrict__ out) {
    __shared__ float sm[512];
    int tid = threadIdx.x;
    sm[tid] = g_partial[tid];
    __syncthreads();
#pragma unroll
    for (int s = 256; s > 0; s >>= 1) {
        if (tid < s) sm[tid] += sm[tid + s];
        __syncthreads();
    }
    // loss = 0.5 * mean_{B*P*K}( sum_d (.)^2 / SIGMA ) = total * 0.5*100/16384
    if (tid == 0) out[0] = sm[0] * (50.0f / 16384.0f);
}

extern "C" void kernel_launch(void* const* d_in, const int* in_sizes, int n_in,
                              void* d_out, int out_size) {
    const float* noisy = (const float*)d_in[0];
    const float* clean = (const float*)d_in[1];
    const int*   sidx  = (const int*)d_in[2];
    const float* Wf1 = (const float*)d_in[3];
    const float* bf1 = (const float*)d_in[4];
    const float* Wf2 = (const float*)d_in[5];
    const float* bf2 = (const float*)d_in[6];
    const float* Ws1 = (const float*)d_in[7];
    const float* bs1 = (const float*)d_in[8];
    const float* Ws2 = (const float*)d_in[9];
    const float* bs2 = (const float*)d_in[10];
    const float* Ws3 = (const float*)d_in[11];
    const float* bs3 = (const float*)d_in[12];
    float* out = (float*)d_out;

    k0_pack<<<(BB * NN + 255) / 256, 256>>>(noisy, clean);
    k1_feat<<<BB * PP, 128>>>(noisy, sidx, Wf1, bf1, Wf2, bf2, Ws1, bs1);
    k2_knn1<<<BB * PP, 256>>>();
    k3_mlp<<<BB * PP / 2, 256>>>(Ws1, Ws2, bs2, Ws3, bs3);
    k4_knn2<<<BB * PP, 256>>>();
    k5_reduce<<<1, 512>>>(out);
}